// round 1
// baseline (speedup 1.0000x reference)
#include <cuda_runtime.h>

#define NN 100000
#define NE 3200000
#define NG 1000

// ---------------- scratch (device globals: allowed) ----------------
__device__ __align__(16) float g_msg1[NN * 16];
__device__ __align__(16) float g_root1[NN * 16];
__device__ __align__(16) float g_agg1[NN * 16];
__device__ __align__(16) float g_msg2[NN * 32];
__device__ __align__(16) float g_root2[NN * 32];
__device__ __align__(16) float g_agg2[NN * 32];
__device__ __align__(16) float g_msg3[NN * 32];
__device__ __align__(16) float g_root3[NN * 32];
__device__ __align__(16) float g_agg3[NN * 32];
__device__ __align__(16) float g_pooled[NG * 32];
__device__ int g_ei64;
__device__ int g_b64;

// ---------------- helpers ----------------
__device__ __forceinline__ void red4(float* addr, float4 v) {
    asm volatile("red.global.add.v4.f32 [%0], {%1,%2,%3,%4};"
                 :: "l"(addr), "f"(v.x), "f"(v.y), "f"(v.z), "f"(v.w) : "memory");
}

// Detect whether edge_index / batch are int64 or int32 (JAX x64-config ambiguity).
// For int64 data (values < 2^31, nonneg), every odd int32 word is the zero high half.
__global__ void k_detect(const int* __restrict__ ei, const int* __restrict__ batch) {
    if (blockIdx.x != 0 || threadIdx.x != 0) return;
    // edge_index: sample 64 odd positions in [1, 2*NE) (valid for both dtypes)
    int all0 = 1;
    for (int j = 0; j < 64; j++) {
        long long p = 1 + 2LL * j * 49999;   // odd, max 6,299,875 < 6.4M
        if (ei[p] != 0) { all0 = 0; break; }
    }
    g_ei64 = all0;
    // batch: sorted; sample odd positions near the TOP of [0, NN) — for int32 these
    // are graph ids ~999 (nonzero); for int64 they are high words (~graph 500 -> 0).
    int all0b = 1;
    for (int j = 0; j < 32; j++) {
        int p = (NN - 1) - 2 * j;            // 99999, 99997, ... (odd)
        if (batch[p] != 0) { all0b = 0; break; }
    }
    g_b64 = all0b;
}

// ---------------- layer 1 node matmuls: msg1 = x@W1n, root1 = x@W1r -----------
__global__ __launch_bounds__(256) void k_lin1(const float* __restrict__ x,
                                              const float* __restrict__ W1r,
                                              const float* __restrict__ W1n) {
    __shared__ float4 sWn[512];  // 128x16
    __shared__ float4 sWr[512];
    int tid = threadIdx.x;
    for (int i = tid; i < 512; i += 256) {
        sWn[i] = ((const float4*)W1n)[i];
        sWr[i] = ((const float4*)W1r)[i];
    }
    __syncthreads();
    int n = blockIdx.x * 256 + tid;
    // zero pooled (1000*32 floats = 8000 float4)
    if (n < 8000) ((float4*)g_pooled)[n] = make_float4(0.f, 0.f, 0.f, 0.f);
    if (n >= NN) return;
    // zero agg1 row
    {
        float4 z = make_float4(0.f, 0.f, 0.f, 0.f);
        float4* a = (float4*)(g_agg1 + n * 16);
        a[0] = z; a[1] = z; a[2] = z; a[3] = z;
    }
    float accn[16], accr[16];
#pragma unroll
    for (int o = 0; o < 16; o++) { accn[o] = 0.f; accr[o] = 0.f; }
    const float4* xr = (const float4*)(x + (long long)n * 128);
#pragma unroll 4
    for (int k4 = 0; k4 < 32; k4++) {
        float4 xv = xr[k4];
        float xs[4] = {xv.x, xv.y, xv.z, xv.w};
#pragma unroll
        for (int kk = 0; kk < 4; kk++) {
            int k = (k4 << 2) + kk;
#pragma unroll
            for (int o4 = 0; o4 < 4; o4++) {
                float4 wn = sWn[(k << 2) + o4];
                float4 wr = sWr[(k << 2) + o4];
                accn[(o4 << 2) + 0] += xs[kk] * wn.x;
                accn[(o4 << 2) + 1] += xs[kk] * wn.y;
                accn[(o4 << 2) + 2] += xs[kk] * wn.z;
                accn[(o4 << 2) + 3] += xs[kk] * wn.w;
                accr[(o4 << 2) + 0] += xs[kk] * wr.x;
                accr[(o4 << 2) + 1] += xs[kk] * wr.y;
                accr[(o4 << 2) + 2] += xs[kk] * wr.z;
                accr[(o4 << 2) + 3] += xs[kk] * wr.w;
            }
        }
    }
    float4* m = (float4*)(g_msg1 + n * 16);
    float4* r = (float4*)(g_root1 + n * 16);
#pragma unroll
    for (int o4 = 0; o4 < 4; o4++) {
        m[o4] = make_float4(accn[o4 * 4], accn[o4 * 4 + 1], accn[o4 * 4 + 2], accn[o4 * 4 + 3]);
        r[o4] = make_float4(accr[o4 * 4], accr[o4 * 4 + 1], accr[o4 * 4 + 2], accr[o4 * 4 + 3]);
    }
}

// ---------------- edge scatter: agg[dst] += msg[src] ----------------
__global__ __launch_bounds__(256) void k_edge16(const void* __restrict__ ei) {
    int t = blockIdx.x * 256 + threadIdx.x;
    int e = t >> 2, q = t & 3;
    if (e >= NE) return;
    int src, dst;
    if (g_ei64) {
        const long long* p = (const long long*)ei;
        src = (int)p[e]; dst = (int)p[NE + e];
    } else {
        const int* p = (const int*)ei;
        src = p[e]; dst = p[NE + e];
    }
    float4 v = *(const float4*)(g_msg1 + src * 16 + q * 4);
    red4(g_agg1 + dst * 16 + q * 4, v);
}

__global__ __launch_bounds__(256) void k_edge32(const void* __restrict__ ei, int layer) {
    int t = blockIdx.x * 256 + threadIdx.x;
    int e = t >> 3, q = t & 7;
    if (e >= NE) return;
    const float* msg = (layer == 2) ? g_msg2 : g_msg3;
    float* agg = (layer == 2) ? g_agg2 : g_agg3;
    int src, dst;
    if (g_ei64) {
        const long long* p = (const long long*)ei;
        src = (int)p[e]; dst = (int)p[NE + e];
    } else {
        const int* p = (const int*)ei;
        src = p[e]; dst = p[NE + e];
    }
    float4 v = *(const float4*)(msg + src * 32 + q * 4);
    red4(agg + dst * 32 + q * 4, v);
}

// ------------- h1 = relu(root1+agg1+b1); msg2=h1@W2n; root2=h1@W2r; zero agg2 -----
__global__ __launch_bounds__(256) void k_node2(const float* __restrict__ b1,
                                               const float* __restrict__ W2r,
                                               const float* __restrict__ W2n) {
    __shared__ float4 sWn[128];  // 16x32
    __shared__ float4 sWr[128];
    __shared__ float sb[16];
    int tid = threadIdx.x;
    if (tid < 128) { sWn[tid] = ((const float4*)W2n)[tid]; sWr[tid] = ((const float4*)W2r)[tid]; }
    if (tid < 16) sb[tid] = b1[tid];
    __syncthreads();
    int n = blockIdx.x * 256 + tid;
    if (n >= NN) return;
    {
        float4 z = make_float4(0.f, 0.f, 0.f, 0.f);
        float4* a = (float4*)(g_agg2 + n * 32);
#pragma unroll
        for (int i = 0; i < 8; i++) a[i] = z;
    }
    float h[16];
    const float4* rr = (const float4*)(g_root1 + n * 16);
    const float4* aa = (const float4*)(g_agg1 + n * 16);
#pragma unroll
    for (int i = 0; i < 4; i++) {
        float4 rv = rr[i]; float4 av = aa[i];
        h[i * 4 + 0] = fmaxf(rv.x + av.x + sb[i * 4 + 0], 0.f);
        h[i * 4 + 1] = fmaxf(rv.y + av.y + sb[i * 4 + 1], 0.f);
        h[i * 4 + 2] = fmaxf(rv.z + av.z + sb[i * 4 + 2], 0.f);
        h[i * 4 + 3] = fmaxf(rv.w + av.w + sb[i * 4 + 3], 0.f);
    }
    float acc[32];
    // nbr pass
#pragma unroll
    for (int o = 0; o < 32; o++) acc[o] = 0.f;
#pragma unroll
    for (int k = 0; k < 16; k++) {
        float hv = h[k];
#pragma unroll
        for (int o4 = 0; o4 < 8; o4++) {
            float4 w = sWn[k * 8 + o4];
            acc[o4 * 4 + 0] += hv * w.x; acc[o4 * 4 + 1] += hv * w.y;
            acc[o4 * 4 + 2] += hv * w.z; acc[o4 * 4 + 3] += hv * w.w;
        }
    }
    float4* m = (float4*)(g_msg2 + n * 32);
#pragma unroll
    for (int o4 = 0; o4 < 8; o4++)
        m[o4] = make_float4(acc[o4 * 4], acc[o4 * 4 + 1], acc[o4 * 4 + 2], acc[o4 * 4 + 3]);
    // root pass
#pragma unroll
    for (int o = 0; o < 32; o++) acc[o] = 0.f;
#pragma unroll
    for (int k = 0; k < 16; k++) {
        float hv = h[k];
#pragma unroll
        for (int o4 = 0; o4 < 8; o4++) {
            float4 w = sWr[k * 8 + o4];
            acc[o4 * 4 + 0] += hv * w.x; acc[o4 * 4 + 1] += hv * w.y;
            acc[o4 * 4 + 2] += hv * w.z; acc[o4 * 4 + 3] += hv * w.w;
        }
    }
    float4* r = (float4*)(g_root2 + n * 32);
#pragma unroll
    for (int o4 = 0; o4 < 8; o4++)
        r[o4] = make_float4(acc[o4 * 4], acc[o4 * 4 + 1], acc[o4 * 4 + 2], acc[o4 * 4 + 3]);
}

// ------------- h2 = relu(root2+agg2+b2); msg3=h2@W3n; root3=h2@W3r; zero agg3 -----
__global__ __launch_bounds__(256) void k_node3(const float* __restrict__ b2,
                                               const float* __restrict__ W3r,
                                               const float* __restrict__ W3n) {
    __shared__ float4 sWn[256];  // 32x32
    __shared__ float4 sWr[256];
    __shared__ float sb[32];
    int tid = threadIdx.x;
    if (tid < 256) { sWn[tid] = ((const float4*)W3n)[tid]; sWr[tid] = ((const float4*)W3r)[tid]; }
    if (tid < 32) sb[tid] = b2[tid];
    __syncthreads();
    int n = blockIdx.x * 256 + tid;
    if (n >= NN) return;
    {
        float4 z = make_float4(0.f, 0.f, 0.f, 0.f);
        float4* a = (float4*)(g_agg3 + n * 32);
#pragma unroll
        for (int i = 0; i < 8; i++) a[i] = z;
    }
    float h[32];
    const float4* rr = (const float4*)(g_root2 + n * 32);
    const float4* aa = (const float4*)(g_agg2 + n * 32);
#pragma unroll
    for (int i = 0; i < 8; i++) {
        float4 rv = rr[i]; float4 av = aa[i];
        h[i * 4 + 0] = fmaxf(rv.x + av.x + sb[i * 4 + 0], 0.f);
        h[i * 4 + 1] = fmaxf(rv.y + av.y + sb[i * 4 + 1], 0.f);
        h[i * 4 + 2] = fmaxf(rv.z + av.z + sb[i * 4 + 2], 0.f);
        h[i * 4 + 3] = fmaxf(rv.w + av.w + sb[i * 4 + 3], 0.f);
    }
    float acc[32];
#pragma unroll
    for (int o = 0; o < 32; o++) acc[o] = 0.f;
#pragma unroll 8
    for (int k = 0; k < 32; k++) {
        float hv = h[k];
#pragma unroll
        for (int o4 = 0; o4 < 8; o4++) {
            float4 w = sWn[k * 8 + o4];
            acc[o4 * 4 + 0] += hv * w.x; acc[o4 * 4 + 1] += hv * w.y;
            acc[o4 * 4 + 2] += hv * w.z; acc[o4 * 4 + 3] += hv * w.w;
        }
    }
    float4* m = (float4*)(g_msg3 + n * 32);
#pragma unroll
    for (int o4 = 0; o4 < 8; o4++)
        m[o4] = make_float4(acc[o4 * 4], acc[o4 * 4 + 1], acc[o4 * 4 + 2], acc[o4 * 4 + 3]);
#pragma unroll
    for (int o = 0; o < 32; o++) acc[o] = 0.f;
#pragma unroll 8
    for (int k = 0; k < 32; k++) {
        float hv = h[k];
#pragma unroll
        for (int o4 = 0; o4 < 8; o4++) {
            float4 w = sWr[k * 8 + o4];
            acc[o4 * 4 + 0] += hv * w.x; acc[o4 * 4 + 1] += hv * w.y;
            acc[o4 * 4 + 2] += hv * w.z; acc[o4 * 4 + 3] += hv * w.w;
        }
    }
    float4* r = (float4*)(g_root3 + n * 32);
#pragma unroll
    for (int o4 = 0; o4 < 8; o4++)
        r[o4] = make_float4(acc[o4 * 4], acc[o4 * 4 + 1], acc[o4 * 4 + 2], acc[o4 * 4 + 3]);
}

// ------------- h3 = relu(root3+agg3+b3); pooled[batch[n]] += h3 ----------------
__global__ __launch_bounds__(256) void k_pool(const float* __restrict__ b3,
                                              const void* __restrict__ batch) {
    __shared__ float sb[32];
    int tid = threadIdx.x;
    if (tid < 32) sb[tid] = b3[tid];
    __syncthreads();
    int n = blockIdx.x * 256 + tid;
    if (n >= NN) return;
    int g;
    if (g_b64) g = (int)((const long long*)batch)[n];
    else       g = ((const int*)batch)[n];
    const float4* rr = (const float4*)(g_root3 + n * 32);
    const float4* aa = (const float4*)(g_agg3 + n * 32);
#pragma unroll
    for (int i = 0; i < 8; i++) {
        float4 rv = rr[i]; float4 av = aa[i];
        float4 h;
        h.x = fmaxf(rv.x + av.x + sb[i * 4 + 0], 0.f);
        h.y = fmaxf(rv.y + av.y + sb[i * 4 + 1], 0.f);
        h.z = fmaxf(rv.z + av.z + sb[i * 4 + 2], 0.f);
        h.w = fmaxf(rv.w + av.w + sb[i * 4 + 3], 0.f);
        red4(g_pooled + g * 32 + i * 4, h);
    }
}

// ------------- out = pooled @ Wlin + blin ----------------
__global__ __launch_bounds__(64) void k_final(const float* __restrict__ Wlin,
                                              const float* __restrict__ blin,
                                              float* __restrict__ out) {
    __shared__ float sW[32 * 64];
    int tid = threadIdx.x;
    for (int i = tid; i < 2048; i += 64) sW[i] = Wlin[i];
    __syncthreads();
    int g = blockIdx.x;
    float acc = blin[tid];
    const float* p = g_pooled + g * 32;
#pragma unroll
    for (int k = 0; k < 32; k++) acc += p[k] * sW[k * 64 + tid];
    out[g * 64 + tid] = acc;
}

// ---------------- launch ----------------
extern "C" void kernel_launch(void* const* d_in, const int* in_sizes, int n_in,
                              void* d_out, int out_size) {
    const float* x    = (const float*)d_in[0];
    const void*  ei   = d_in[1];
    const void*  batch = d_in[2];
    const float* W1r = (const float*)d_in[3];
    const float* W1n = (const float*)d_in[4];
    const float* b1  = (const float*)d_in[5];
    const float* W2r = (const float*)d_in[6];
    const float* W2n = (const float*)d_in[7];
    const float* b2  = (const float*)d_in[8];
    const float* W3r = (const float*)d_in[9];
    const float* W3n = (const float*)d_in[10];
    const float* b3  = (const float*)d_in[11];
    const float* Wlin = (const float*)d_in[12];
    const float* blin = (const float*)d_in[13];
    float* out = (float*)d_out;

    const int NODE_BLKS = (NN + 255) / 256;

    k_detect<<<1, 1>>>((const int*)ei, (const int*)batch);
    k_lin1<<<NODE_BLKS, 256>>>(x, W1r, W1n);
    k_edge16<<<(NE * 4 + 255) / 256, 256>>>(ei);
    k_node2<<<NODE_BLKS, 256>>>(b1, W2r, W2n);
    k_edge32<<<(NE * 8 + 255) / 256, 256>>>(ei, 2);
    k_node3<<<NODE_BLKS, 256>>>(b2, W3r, W3n);
    k_edge32<<<(NE * 8 + 255) / 256, 256>>>(ei, 3);
    k_pool<<<NODE_BLKS, 256>>>(b3, batch);
    k_final<<<NG, 64>>>(Wlin, blin, out);
}